// round 1
// baseline (speedup 1.0000x reference)
#include <cuda_runtime.h>

// Problem constants
#define Bn     8192
#define F0n    2048
#define En     512
#define OUTn   2048
#define Wn     3584      // F0 + 3*E
#define NNZ_E  8192
#define NNZ_M  16384

// ---------------------------------------------------------------------------
// Device scratch (no allocation allowed)
// ---------------------------------------------------------------------------
// ht: feature-major activation buffer [Wn][Bn]  (117 MB, fits L2)
__device__ float g_ht[(size_t)Wn * Bn];

// CSR build scratch for 4 sparse weights (3 embed + main)
__device__ int  g_cnt[4 * 2048];
__device__ int  g_ptr[4 * 2049];
__device__ int  g_cur[4 * 2048];
__device__ int2 g_ent[4 * 16384];   // packed {col, float_bits(val)}

// ---------------------------------------------------------------------------
// CSR build kernels
// ---------------------------------------------------------------------------
__global__ void zero_cnt_k() {
    int i = blockIdx.x * blockDim.x + threadIdx.x;
    if (i < 4 * 2048) g_cnt[i] = 0;
}

__global__ void count_k(const int* __restrict__ r0, const int* __restrict__ r1,
                        const int* __restrict__ r2, const int* __restrict__ rm) {
    int k = blockIdx.x * blockDim.x + threadIdx.x;
    if (k < NNZ_E) {
        atomicAdd(&g_cnt[0 * 2048 + r0[k]], 1);
        atomicAdd(&g_cnt[1 * 2048 + r1[k]], 1);
        atomicAdd(&g_cnt[2 * 2048 + r2[k]], 1);
    }
    if (k < NNZ_M) atomicAdd(&g_cnt[3 * 2048 + rm[k]], 1);
}

// One block per weight: exclusive scan of row counts -> row_ptr, row cursors.
__global__ void scan_k() {
    int w = blockIdx.x;
    int nrows = (w < 3) ? En : OUTn;
    int per = nrows / 256;               // 2 or 8
    int t = threadIdx.x;
    __shared__ int s[256];

    int base = w * 2048;
    int local[8];
    int sum = 0;
    for (int j = 0; j < per; j++) {
        local[j] = g_cnt[base + t * per + j];
        sum += local[j];
    }
    s[t] = sum;
    __syncthreads();
    // Hillis-Steele inclusive scan over 256 partials
    for (int off = 1; off < 256; off <<= 1) {
        int v = (t >= off) ? s[t - off] : 0;
        __syncthreads();
        s[t] += v;
        __syncthreads();
    }
    int run = s[t] - sum;                // exclusive prefix for this thread
    for (int j = 0; j < per; j++) {
        g_ptr[w * 2049 + t * per + j] = run;
        g_cur[base + t * per + j]     = run;
        run += local[j];
    }
    if (t == 255) g_ptr[w * 2049 + nrows] = s[255];
}

__global__ void scatter_k(const int* __restrict__ r0, const int* __restrict__ c0, const float* __restrict__ v0,
                          const int* __restrict__ r1, const int* __restrict__ c1, const float* __restrict__ v1,
                          const int* __restrict__ r2, const int* __restrict__ c2, const float* __restrict__ v2,
                          const int* __restrict__ rm, const int* __restrict__ cm, const float* __restrict__ vm) {
    int k = blockIdx.x * blockDim.x + threadIdx.x;
    if (k < NNZ_E) {
        int p;
        p = atomicAdd(&g_cur[0 * 2048 + r0[k]], 1);
        g_ent[0 * 16384 + p] = make_int2(c0[k], __float_as_int(v0[k]));
        p = atomicAdd(&g_cur[1 * 2048 + r1[k]], 1);
        g_ent[1 * 16384 + p] = make_int2(c1[k], __float_as_int(v1[k]));
        p = atomicAdd(&g_cur[2 * 2048 + r2[k]], 1);
        g_ent[2 * 16384 + p] = make_int2(c2[k], __float_as_int(v2[k]));
    }
    if (k < NNZ_M) {
        int p = atomicAdd(&g_cur[3 * 2048 + rm[k]], 1);
        g_ent[3 * 16384 + p] = make_int2(cm[k], __float_as_int(vm[k]));
    }
}

// ---------------------------------------------------------------------------
// Transpose x [B, F0] row-major -> ht [F0][B] feature-major
// ---------------------------------------------------------------------------
__global__ void transpose_k(const float* __restrict__ x) {
    __shared__ float tile[32][33];
    int c = blockIdx.x * 32 + threadIdx.x;
    int b = blockIdx.y * 32 + threadIdx.y;
#pragma unroll
    for (int j = 0; j < 32; j += 8)
        tile[threadIdx.y + j][threadIdx.x] = x[(size_t)(b + j) * F0n + c];
    __syncthreads();
    int c2 = blockIdx.x * 32 + threadIdx.y;
    int b2 = blockIdx.y * 32 + threadIdx.x;
#pragma unroll
    for (int j = 0; j < 32; j += 8)
        g_ht[(size_t)(c2 + j) * Bn + b2] = tile[threadIdx.x][threadIdx.y + j];
}

// ---------------------------------------------------------------------------
// One embed level: ht[fo + r][:] = sum_k vals[k] * ht[cols[k]][:]  (CSR row r)
// grid: (E rows, 8 b-chunks of 1024), block 256, each thread owns 4 b's.
// ---------------------------------------------------------------------------
__global__ void level_k(int w, int fo) {
    int r = blockIdx.x;
    int b = blockIdx.y * 1024 + threadIdx.x * 4;
    int s = g_ptr[w * 2049 + r];
    int e = g_ptr[w * 2049 + r + 1];
    const int2* ent = g_ent + w * 16384;

    float4 acc = make_float4(0.f, 0.f, 0.f, 0.f);
    for (int k = s; k < e; k++) {
        int2 cv = __ldg(&ent[k]);                 // warp-uniform broadcast
        float v = __int_as_float(cv.y);
        float4 h = *reinterpret_cast<const float4*>(&g_ht[(size_t)cv.x * Bn + b]);
        acc.x += v * h.x;
        acc.y += v * h.y;
        acc.z += v * h.z;
        acc.w += v * h.w;
    }
    *reinterpret_cast<float4*>(&g_ht[(size_t)(fo + r) * Bn + b]) = acc;
}

// ---------------------------------------------------------------------------
// MAIN layer with smem-staged transpose so the b-major output write coalesces.
// Block = (8 output rows, 1024 b's). grid (OUT/8 = 256, 8).
// ---------------------------------------------------------------------------
#define RT 8
__global__ void main_k(float* __restrict__ out) {
    __shared__ float tileS[RT * 1025];
    int r0 = blockIdx.x * RT;
    int b0 = blockIdx.y * 1024;
    int l4 = threadIdx.x * 4;
    const int2* ent = g_ent + 3 * 16384;

    for (int j = 0; j < RT; j++) {
        int r = r0 + j;
        int s = g_ptr[3 * 2049 + r];
        int e = g_ptr[3 * 2049 + r + 1];
        float4 acc = make_float4(0.f, 0.f, 0.f, 0.f);
        for (int k = s; k < e; k++) {
            int2 cv = __ldg(&ent[k]);
            float v = __int_as_float(cv.y);
            float4 h = *reinterpret_cast<const float4*>(&g_ht[(size_t)cv.x * Bn + b0 + l4]);
            acc.x += v * h.x;
            acc.y += v * h.y;
            acc.z += v * h.z;
            acc.w += v * h.w;
        }
        tileS[j * 1025 + l4 + 0] = acc.x;
        tileS[j * 1025 + l4 + 1] = acc.y;
        tileS[j * 1025 + l4 + 2] = acc.z;
        tileS[j * 1025 + l4 + 3] = acc.w;
    }
    __syncthreads();
    // Transposed write-out: each warp writes 4 output rows x 32B segments.
    for (int t = threadIdx.x; t < RT * 1024; t += 256) {
        int j = t & (RT - 1);
        int brow = t >> 3;
        out[(size_t)(b0 + brow) * OUTn + r0 + j] = tileS[j * 1025 + brow];
    }
}

// ---------------------------------------------------------------------------
// Launch
// ---------------------------------------------------------------------------
extern "C" void kernel_launch(void* const* d_in, const int* in_sizes, int n_in,
                              void* d_out, int out_size) {
    const float* x  = (const float*)d_in[0];
    const int*   er0 = (const int*)d_in[1];
    const int*   ec0 = (const int*)d_in[2];
    const float* ev0 = (const float*)d_in[3];
    const int*   er1 = (const int*)d_in[4];
    const int*   ec1 = (const int*)d_in[5];
    const float* ev1 = (const float*)d_in[6];
    const int*   er2 = (const int*)d_in[7];
    const int*   ec2 = (const int*)d_in[8];
    const float* ev2 = (const float*)d_in[9];
    const int*   mr  = (const int*)d_in[10];
    const int*   mc  = (const int*)d_in[11];
    const float* mv  = (const float*)d_in[12];
    float* out = (float*)d_out;

    // CSR build (tiny)
    zero_cnt_k<<<32, 256>>>();
    count_k<<<64, 256>>>(er0, er1, er2, mr);
    scan_k<<<4, 256>>>();
    scatter_k<<<64, 256>>>(er0, ec0, ev0, er1, ec1, ev1, er2, ec2, ev2, mr, mc, mv);

    // x -> feature-major ht
    transpose_k<<<dim3(F0n / 32, Bn / 32), dim3(32, 8)>>>(x);

    // Recursion chain
    level_k<<<dim3(En, 8), 256>>>(0, F0n);
    level_k<<<dim3(En, 8), 256>>>(1, F0n + En);
    level_k<<<dim3(En, 8), 256>>>(2, F0n + 2 * En);

    // MAIN
    main_k<<<dim3(OUTn / RT, 8), 256>>>(out);
}

// round 2
// speedup vs baseline: 1.0011x; 1.0011x over previous
#include <cuda_runtime.h>

// Problem constants
#define Bn     8192
#define Bh     4096      // half-batch processed per pass (ht half fits L2)
#define F0n    2048
#define En     512
#define OUTn   2048
#define Wn     3584      // F0 + 3*E
#define NNZ_E  8192
#define NNZ_M  16384

// ---------------------------------------------------------------------------
// Device scratch (no allocation allowed)
// ---------------------------------------------------------------------------
// ht: feature-major activation buffer for ONE half-batch [Wn][Bh] (58.7 MB, L2-resident)
__device__ float g_ht[(size_t)Wn * Bh];

// CSR build scratch for 4 sparse weights (3 embed + main)
__device__ int  g_cnt[4 * 2048];
__device__ int  g_ptr[4 * 2049];
__device__ int  g_cur[4 * 2048];
__device__ int2 g_ent[4 * 16384];   // packed {col, float_bits(val)}

// ---------------------------------------------------------------------------
// CSR build kernels (tiny, run once)
// ---------------------------------------------------------------------------
__global__ void zero_cnt_k() {
    int i = blockIdx.x * blockDim.x + threadIdx.x;
    if (i < 4 * 2048) g_cnt[i] = 0;
}

__global__ void count_k(const int* __restrict__ r0, const int* __restrict__ r1,
                        const int* __restrict__ r2, const int* __restrict__ rm) {
    int k = blockIdx.x * blockDim.x + threadIdx.x;
    if (k < NNZ_E) {
        atomicAdd(&g_cnt[0 * 2048 + r0[k]], 1);
        atomicAdd(&g_cnt[1 * 2048 + r1[k]], 1);
        atomicAdd(&g_cnt[2 * 2048 + r2[k]], 1);
    }
    if (k < NNZ_M) atomicAdd(&g_cnt[3 * 2048 + rm[k]], 1);
}

// One block per weight: exclusive scan of row counts -> row_ptr, row cursors.
__global__ void scan_k() {
    int w = blockIdx.x;
    int nrows = (w < 3) ? En : OUTn;
    int per = nrows / 256;               // 2 or 8
    int t = threadIdx.x;
    __shared__ int s[256];

    int base = w * 2048;
    int local[8];
    int sum = 0;
    for (int j = 0; j < per; j++) {
        local[j] = g_cnt[base + t * per + j];
        sum += local[j];
    }
    s[t] = sum;
    __syncthreads();
    for (int off = 1; off < 256; off <<= 1) {
        int v = (t >= off) ? s[t - off] : 0;
        __syncthreads();
        s[t] += v;
        __syncthreads();
    }
    int run = s[t] - sum;                // exclusive prefix for this thread
    for (int j = 0; j < per; j++) {
        g_ptr[w * 2049 + t * per + j] = run;
        g_cur[base + t * per + j]     = run;
        run += local[j];
    }
    if (t == 255) g_ptr[w * 2049 + nrows] = s[255];
}

__global__ void scatter_k(const int* __restrict__ r0, const int* __restrict__ c0, const float* __restrict__ v0,
                          const int* __restrict__ r1, const int* __restrict__ c1, const float* __restrict__ v1,
                          const int* __restrict__ r2, const int* __restrict__ c2, const float* __restrict__ v2,
                          const int* __restrict__ rm, const int* __restrict__ cm, const float* __restrict__ vm) {
    int k = blockIdx.x * blockDim.x + threadIdx.x;
    if (k < NNZ_E) {
        int p;
        p = atomicAdd(&g_cur[0 * 2048 + r0[k]], 1);
        g_ent[0 * 16384 + p] = make_int2(c0[k], __float_as_int(v0[k]));
        p = atomicAdd(&g_cur[1 * 2048 + r1[k]], 1);
        g_ent[1 * 16384 + p] = make_int2(c1[k], __float_as_int(v1[k]));
        p = atomicAdd(&g_cur[2 * 2048 + r2[k]], 1);
        g_ent[2 * 16384 + p] = make_int2(c2[k], __float_as_int(v2[k]));
    }
    if (k < NNZ_M) {
        int p = atomicAdd(&g_cur[3 * 2048 + rm[k]], 1);
        g_ent[3 * 16384 + p] = make_int2(cm[k], __float_as_int(vm[k]));
    }
}

// ---------------------------------------------------------------------------
// Transpose x half [Bh, F0] -> ht [F0][Bh] feature-major
// ---------------------------------------------------------------------------
__global__ void transpose_k(const float* __restrict__ x, int b0g) {
    __shared__ float tile[32][33];
    int c = blockIdx.x * 32 + threadIdx.x;
    int b = blockIdx.y * 32 + threadIdx.y;   // local b within half
#pragma unroll
    for (int j = 0; j < 32; j += 8)
        tile[threadIdx.y + j][threadIdx.x] = x[(size_t)(b0g + b + j) * F0n + c];
    __syncthreads();
    int c2 = blockIdx.x * 32 + threadIdx.y;
    int b2 = blockIdx.y * 32 + threadIdx.x;
#pragma unroll
    for (int j = 0; j < 32; j += 8)
        g_ht[(size_t)(c2 + j) * Bh + b2] = tile[threadIdx.x][threadIdx.y + j];
}

// ---------------------------------------------------------------------------
// One embed level on the half-batch: ht[fo+r][:] = sum_k v * ht[col][:]
// grid (E rows, Bh/1024 chunks), block 256, thread owns 4 b's (float4).
// ---------------------------------------------------------------------------
__global__ void level_k(int w, int fo) {
    int r = blockIdx.x;
    int b = blockIdx.y * 1024 + threadIdx.x * 4;
    int s = g_ptr[w * 2049 + r];
    int e = g_ptr[w * 2049 + r + 1];
    const int2* ent = g_ent + w * 16384;

    float4 acc = make_float4(0.f, 0.f, 0.f, 0.f);
    for (int k = s; k < e; k++) {
        int2 cv = __ldg(&ent[k]);
        float v = __int_as_float(cv.y);
        float4 h = *reinterpret_cast<const float4*>(&g_ht[(size_t)cv.x * Bh + b]);
        acc.x += v * h.x;
        acc.y += v * h.y;
        acc.z += v * h.z;
        acc.w += v * h.w;
    }
    *reinterpret_cast<float4*>(&g_ht[(size_t)(fo + r) * Bh + b]) = acc;
}

// ---------------------------------------------------------------------------
// MAIN on the half-batch, smem-staged transpose for coalesced b-major writes.
// Block = (8 output rows, 1024 b's). grid (OUT/8, Bh/1024).
// ---------------------------------------------------------------------------
#define RT 8
__global__ void main_k(float* __restrict__ out, int b0g) {
    __shared__ float tileS[RT * 1025];
    int r0 = blockIdx.x * RT;
    int b0 = blockIdx.y * 1024;              // local b within half
    int l4 = threadIdx.x * 4;
    const int2* ent = g_ent + 3 * 16384;

    for (int j = 0; j < RT; j++) {
        int r = r0 + j;
        int s = g_ptr[3 * 2049 + r];
        int e = g_ptr[3 * 2049 + r + 1];
        float4 acc = make_float4(0.f, 0.f, 0.f, 0.f);
        for (int k = s; k < e; k++) {
            int2 cv = __ldg(&ent[k]);
            float v = __int_as_float(cv.y);
            float4 h = *reinterpret_cast<const float4*>(&g_ht[(size_t)cv.x * Bh + b0 + l4]);
            acc.x += v * h.x;
            acc.y += v * h.y;
            acc.z += v * h.z;
            acc.w += v * h.w;
        }
        tileS[j * 1025 + l4 + 0] = acc.x;
        tileS[j * 1025 + l4 + 1] = acc.y;
        tileS[j * 1025 + l4 + 2] = acc.z;
        tileS[j * 1025 + l4 + 3] = acc.w;
    }
    __syncthreads();
    for (int t = threadIdx.x; t < RT * 1024; t += 256) {
        int j = t & (RT - 1);
        int brow = t >> 3;
        out[(size_t)(b0g + b0 + brow) * OUTn + r0 + j] = tileS[j * 1025 + brow];
    }
}

// ---------------------------------------------------------------------------
// Launch
// ---------------------------------------------------------------------------
extern "C" void kernel_launch(void* const* d_in, const int* in_sizes, int n_in,
                              void* d_out, int out_size) {
    const float* x  = (const float*)d_in[0];
    const int*   er0 = (const int*)d_in[1];
    const int*   ec0 = (const int*)d_in[2];
    const float* ev0 = (const float*)d_in[3];
    const int*   er1 = (const int*)d_in[4];
    const int*   ec1 = (const int*)d_in[5];
    const float* ev1 = (const float*)d_in[6];
    const int*   er2 = (const int*)d_in[7];
    const int*   ec2 = (const int*)d_in[8];
    const float* ev2 = (const float*)d_in[9];
    const int*   mr  = (const int*)d_in[10];
    const int*   mc  = (const int*)d_in[11];
    const float* mv  = (const float*)d_in[12];
    float* out = (float*)d_out;

    // CSR build (tiny, once)
    zero_cnt_k<<<32, 256>>>();
    count_k<<<64, 256>>>(er0, er1, er2, mr);
    scan_k<<<4, 256>>>();
    scatter_k<<<64, 256>>>(er0, ec0, ev0, er1, ec1, ev1, er2, ec2, ev2, mr, mc, mv);

    // Two half-batch passes; ht half (58.7 MB) stays L2-resident.
    for (int h = 0; h < 2; h++) {
        int b0g = h * Bh;
        transpose_k<<<dim3(F0n / 32, Bh / 32), dim3(32, 8)>>>(x, b0g);
        level_k<<<dim3(En, Bh / 1024), 256>>>(0, F0n);
        level_k<<<dim3(En, Bh / 1024), 256>>>(1, F0n + En);
        level_k<<<dim3(En, Bh / 1024), 256>>>(2, F0n + 2 * En);
        main_k<<<dim3(OUTn / RT, Bh / 1024), 256>>>(out, b0g);
    }
}